// round 16
// baseline (speedup 1.0000x reference)
#include <cuda_runtime.h>
#include <cuda_bf16.h>
#include <math.h>

// ---------------- problem constants ----------------
#define F_IN   256
#define HEADS  8
#define HID    8
#define D1     64
#define CLS    40
#define NEG_SLOPE 0.2f

// ---------------- scratch layout ----------------
#define OFF_H1      0ull                 // N*64 floats
#define OFF_AS1     6400000ull           // N*8
#define OFF_AD1     7200000ull           // N*8
#define OFF_H2      8000000ull           // N*40
#define OFF_AS2     12000000ull          // N
#define OFF_AD2     12100000ull          // N
#define OFF_AGG1    12200000ull          // N*64 (normalized, written by gather1)
// int regions (indices into (int*)g_scratch)
#define ICNT        18600000u            // N
#define IROW        18800000u            // N+1
#define ICUR        19000000u            // N
#define ICSR        19200000u            // Etot
#define IPART       21200000u            // <= 1024
#define TOTAL_SCR   23500000ull

__device__ __align__(16) float g_scratch[TOTAL_SCR];

__device__ __forceinline__ float lrelu(float v) { return v > 0.f ? v : NEG_SLOPE * v; }

// ---------------- CSR build ----------------
__global__ void zero_int_kernel(int N) {
    int* gi = (int*)g_scratch;
    int i = blockIdx.x * blockDim.x + threadIdx.x;
    int stride = gridDim.x * blockDim.x;
    for (; i < 2 * N; i += stride) {
        if (i < N) gi[ICNT + i] = 0;
        else       gi[ICUR + (i - N)] = 0;
    }
}

__global__ void hist_kernel(const int* __restrict__ ei, int E, int Etot, int N) {
    int e = blockIdx.x * blockDim.x + threadIdx.x;
    if (e >= Etot) return;
    int d = (e < E) ? ei[E + e] : (e - E);
    if ((unsigned)d >= (unsigned)N) return;
    atomicAdd((int*)g_scratch + ICNT + d, 1);
}

__global__ void scanA_kernel(int N) {
    __shared__ int sh[1024];
    int* gi = (int*)g_scratch;
    int t = threadIdx.x, b = blockIdx.x;
    int i = b * 1024 + t;
    int v = (i < N) ? gi[ICNT + i] : 0;
    sh[t] = v;
    __syncthreads();
    for (int off = 1; off < 1024; off <<= 1) {
        int x = (t >= off) ? sh[t - off] : 0;
        __syncthreads();
        sh[t] += x;
        __syncthreads();
    }
    if (i < N) gi[IROW + i] = sh[t] - v;
    if (t == 1023) gi[IPART + b] = sh[1023];
}

__global__ void scanB_kernel(int nb) {
    __shared__ int sh[1024];
    int* gi = (int*)g_scratch;
    int t = threadIdx.x;
    int v = (t < nb) ? gi[IPART + t] : 0;
    sh[t] = v;
    __syncthreads();
    for (int off = 1; off < 1024; off <<= 1) {
        int x = (t >= off) ? sh[t - off] : 0;
        __syncthreads();
        sh[t] += x;
        __syncthreads();
    }
    if (t < nb) gi[IPART + t] = sh[t] - v;
}

__global__ void scanC_kernel(int N, int Etot) {
    int* gi = (int*)g_scratch;
    int i = blockIdx.x * blockDim.x + threadIdx.x;
    if (i < N) gi[IROW + i] += gi[IPART + (i >> 10)];
    if (i == 0) gi[IROW + N] = Etot;
}

__global__ void scatter_kernel(const int* __restrict__ ei, int E, int Etot, int N) {
    int e = blockIdx.x * blockDim.x + threadIdx.x;
    if (e >= Etot) return;
    int s, d;
    if (e < E) { s = ei[e]; d = ei[E + e]; } else { s = d = e - E; }
    if ((unsigned)s >= (unsigned)N || (unsigned)d >= (unsigned)N) return;
    int* gi = (int*)g_scratch;
    int pos = atomicAdd(gi + ICUR + d, 1);
    gi[ICSR + gi[IROW + d] + pos] = s;
}

// ---------------- layer 1 GEMM (register tiled) + attention logits ----------------
// Tile: 256 nodes x 64 outs. 256 threads: r=t>>3 (8-node group), c=t&7 (head).
__global__ void gemm1_kernel(const float* __restrict__ x, const float* __restrict__ W1,
                             const float* __restrict__ a_src, const float* __restrict__ a_dst,
                             int N) {
    __shared__ __align__(16) float xs[256 * 33];
    __shared__ __align__(16) float Ws[32 * 68];
    int t = threadIdx.x;
    int node0 = blockIdx.x * 256;
    int r = t >> 3, c = t & 7;

    float acc[8][8];
    #pragma unroll
    for (int i = 0; i < 8; i++)
        #pragma unroll
        for (int j = 0; j < 8; j++) acc[i][j] = 0.f;

    for (int kt = 0; kt < 8; kt++) {
        __syncthreads();
        #pragma unroll
        for (int p = 0; p < 8; p++) {
            int i = t + p * 256;
            int nl = i >> 3, q = i & 7;
            int nd = node0 + nl;
            float4 v = make_float4(0.f, 0.f, 0.f, 0.f);
            if (nd < N) v = ((const float4*)x)[(size_t)nd * 64 + kt * 8 + q];
            float* dp = &xs[nl * 33 + q * 4];
            dp[0] = v.x; dp[1] = v.y; dp[2] = v.z; dp[3] = v.w;
        }
        #pragma unroll
        for (int p = 0; p < 2; p++) {
            int i = t + p * 256;
            int k = i >> 4, o4 = i & 15;
            float4 v = ((const float4*)W1)[(size_t)(kt * 32 + k) * 16 + o4];
            float* dp = &Ws[k * 68 + o4 * 4];
            dp[0] = v.x; dp[1] = v.y; dp[2] = v.z; dp[3] = v.w;
        }
        __syncthreads();

        #pragma unroll 4
        for (int kk = 0; kk < 32; kk++) {
            float wv[8];
            *(float4*)wv       = *(const float4*)&Ws[kk * 68 + c * 8];
            *(float4*)(wv + 4) = *(const float4*)&Ws[kk * 68 + c * 8 + 4];
            float xv[8];
            #pragma unroll
            for (int i = 0; i < 8; i++) xv[i] = xs[(r * 8 + i) * 33 + kk];
            #pragma unroll
            for (int i = 0; i < 8; i++)
                #pragma unroll
                for (int j = 0; j < 8; j++) acc[i][j] = fmaf(xv[i], wv[j], acc[i][j]);
        }
    }

    float asw[8], adw[8];
    #pragma unroll
    for (int j = 0; j < 8; j++) {
        asw[j] = __ldg(&a_src[c * 8 + j]);
        adw[j] = __ldg(&a_dst[c * 8 + j]);
    }
    #pragma unroll
    for (int i = 0; i < 8; i++) {
        int node = node0 + r * 8 + i;
        if (node < N) {
            float* h1 = g_scratch + OFF_H1 + (size_t)node * 64 + c * 8;
            ((float4*)h1)[0] = make_float4(acc[i][0], acc[i][1], acc[i][2], acc[i][3]);
            ((float4*)h1)[1] = make_float4(acc[i][4], acc[i][5], acc[i][6], acc[i][7]);
            float as = 0.f, ad = 0.f;
            #pragma unroll
            for (int j = 0; j < 8; j++) {
                as = fmaf(acc[i][j], asw[j], as);
                ad = fmaf(acc[i][j], adw[j], ad);
            }
            g_scratch[OFF_AS1 + (size_t)node * 8 + c] = as;
            g_scratch[OFF_AD1 + (size_t)node * 8 + c] = ad;
        }
    }
}

// ---------------- layer 1 gather: warp per node, 8 edge-slots x 4 lanes ----------------
// lane l4 = lane&3 owns heads l4 and l4+4; slot = lane>>2 owns edge i0+slot.
__global__ void gather1_kernel(int N) {
    int w = (blockIdx.x * blockDim.x + threadIdx.x) >> 5;
    if (w >= N) return;
    int lane = threadIdx.x & 31;
    int l4 = lane & 3, slot = lane >> 2;
    const int* gi = (const int*)g_scratch;
    int base = gi[IROW + w];
    int deg = gi[IROW + w + 1] - base;
    float ad_a = g_scratch[OFF_AD1 + (size_t)w * 8 + l4];
    float ad_b = g_scratch[OFF_AD1 + (size_t)w * 8 + l4 + 4];

    float acc[16];
    #pragma unroll
    for (int j = 0; j < 16; j++) acc[j] = 0.f;
    float den_a = 0.f, den_b = 0.f;

    for (int i0 = 0; i0 < deg; i0 += 8) {
        int idx = i0 + slot;
        bool valid = idx < deg;
        int s = valid ? gi[ICSR + base + idx] : w;
        float as_a = g_scratch[OFF_AS1 + (size_t)s * 8 + l4];
        float as_b = g_scratch[OFF_AS1 + (size_t)s * 8 + l4 + 4];
        float ex_a = valid ? __expf(lrelu(as_a + ad_a)) : 0.f;
        float ex_b = valid ? __expf(lrelu(as_b + ad_b)) : 0.f;
        const float4* hv = (const float4*)(g_scratch + OFF_H1 + (size_t)s * 64 + l4 * 8);
        float4 v0 = hv[0], v1 = hv[1];
        const float4* hw = (const float4*)(g_scratch + OFF_H1 + (size_t)s * 64 + (l4 + 4) * 8);
        float4 u0 = hw[0], u1 = hw[1];
        acc[0]  = fmaf(ex_a, v0.x, acc[0]);  acc[1]  = fmaf(ex_a, v0.y, acc[1]);
        acc[2]  = fmaf(ex_a, v0.z, acc[2]);  acc[3]  = fmaf(ex_a, v0.w, acc[3]);
        acc[4]  = fmaf(ex_a, v1.x, acc[4]);  acc[5]  = fmaf(ex_a, v1.y, acc[5]);
        acc[6]  = fmaf(ex_a, v1.z, acc[6]);  acc[7]  = fmaf(ex_a, v1.w, acc[7]);
        acc[8]  = fmaf(ex_b, u0.x, acc[8]);  acc[9]  = fmaf(ex_b, u0.y, acc[9]);
        acc[10] = fmaf(ex_b, u0.z, acc[10]); acc[11] = fmaf(ex_b, u0.w, acc[11]);
        acc[12] = fmaf(ex_b, u1.x, acc[12]); acc[13] = fmaf(ex_b, u1.y, acc[13]);
        acc[14] = fmaf(ex_b, u1.z, acc[14]); acc[15] = fmaf(ex_b, u1.w, acc[15]);
        den_a += ex_a; den_b += ex_b;
    }
    // reduce across 8 slots (xor over bits 2,3,4 of lane)
    #pragma unroll
    for (int m = 4; m <= 16; m <<= 1) {
        den_a += __shfl_xor_sync(0xffffffffu, den_a, m);
        den_b += __shfl_xor_sync(0xffffffffu, den_b, m);
        #pragma unroll
        for (int j = 0; j < 16; j++) acc[j] += __shfl_xor_sync(0xffffffffu, acc[j], m);
    }
    if (slot == 0) {
        float inv_a = __frcp_rn(den_a);
        float inv_b = __frcp_rn(den_b);
        float* da = g_scratch + OFF_AGG1 + (size_t)w * 64 + l4 * 8;
        ((float4*)da)[0] = make_float4(acc[0] * inv_a, acc[1] * inv_a, acc[2] * inv_a, acc[3] * inv_a);
        ((float4*)da)[1] = make_float4(acc[4] * inv_a, acc[5] * inv_a, acc[6] * inv_a, acc[7] * inv_a);
        float* db = g_scratch + OFF_AGG1 + (size_t)w * 64 + (l4 + 4) * 8;
        ((float4*)db)[0] = make_float4(acc[8] * inv_b, acc[9] * inv_b, acc[10] * inv_b, acc[11] * inv_b);
        ((float4*)db)[1] = make_float4(acc[12] * inv_b, acc[13] * inv_b, acc[14] * inv_b, acc[15] * inv_b);
    }
}

// ---------------- ELU + layer 2 GEMM (register tiled) + logits ----------------
// Tile: 256 nodes x 40 outs. 256 threads: r=t>>3, c=t&7 (classes c*5..c*5+4).
__global__ void gemm2_kernel(const float* __restrict__ W2, const float* __restrict__ a_src2,
                             const float* __restrict__ a_dst2, const float* __restrict__ b1,
                             int N) {
    __shared__ __align__(16) float xs[256 * 33];
    __shared__ __align__(16) float Ws[32 * 44];
    int t = threadIdx.x;
    int node0 = blockIdx.x * 256;
    int r = t >> 3, c = t & 7;

    float acc[8][5];
    #pragma unroll
    for (int i = 0; i < 8; i++)
        #pragma unroll
        for (int j = 0; j < 5; j++) acc[i][j] = 0.f;

    for (int kt = 0; kt < 2; kt++) {
        __syncthreads();
        #pragma unroll
        for (int p = 0; p < 8; p++) {
            int i = t + p * 256;
            int nl = i >> 3, q = i & 7;
            int nd = node0 + nl;
            float4 v = make_float4(0.f, 0.f, 0.f, 0.f);
            if (nd < N) {
                v = *(const float4*)(g_scratch + OFF_AGG1 + (size_t)nd * 64 + kt * 32 + q * 4);
                float4 bv = *(const float4*)&b1[kt * 32 + q * 4];
                v.x += bv.x; v.y += bv.y; v.z += bv.z; v.w += bv.w;
                v.x = v.x > 0.f ? v.x : expm1f(v.x);
                v.y = v.y > 0.f ? v.y : expm1f(v.y);
                v.z = v.z > 0.f ? v.z : expm1f(v.z);
                v.w = v.w > 0.f ? v.w : expm1f(v.w);
            }
            float* dp = &xs[nl * 33 + q * 4];
            dp[0] = v.x; dp[1] = v.y; dp[2] = v.z; dp[3] = v.w;
        }
        // W chunk: 32 rows x 40 cols = 320 float4 — loop to cover all with 256 threads
        for (int i = t; i < 320; i += 256) {
            int k = i / 10, o4 = i % 10;
            float4 v = ((const float4*)W2)[(size_t)(kt * 32 + k) * 10 + o4];
            float* dp = &Ws[k * 44 + o4 * 4];
            dp[0] = v.x; dp[1] = v.y; dp[2] = v.z; dp[3] = v.w;
        }
        __syncthreads();

        #pragma unroll 4
        for (int kk = 0; kk < 32; kk++) {
            float wv[5];
            #pragma unroll
            for (int j = 0; j < 5; j++) wv[j] = Ws[kk * 44 + c * 5 + j];
            float xv[8];
            #pragma unroll
            for (int i = 0; i < 8; i++) xv[i] = xs[(r * 8 + i) * 33 + kk];
            #pragma unroll
            for (int i = 0; i < 8; i++)
                #pragma unroll
                for (int j = 0; j < 5; j++) acc[i][j] = fmaf(xv[i], wv[j], acc[i][j]);
        }
    }

    float a2s[5], a2d[5];
    #pragma unroll
    for (int j = 0; j < 5; j++) {
        a2s[j] = __ldg(&a_src2[c * 5 + j]);
        a2d[j] = __ldg(&a_dst2[c * 5 + j]);
    }
    #pragma unroll
    for (int i = 0; i < 8; i++) {
        int node = node0 + r * 8 + i;
        float pa = 0.f, pd = 0.f;
        #pragma unroll
        for (int j = 0; j < 5; j++) {
            pa = fmaf(acc[i][j], a2s[j], pa);
            pd = fmaf(acc[i][j], a2d[j], pd);
        }
        #pragma unroll
        for (int o = 4; o >= 1; o >>= 1) {
            pa += __shfl_down_sync(0xffffffffu, pa, o, 8);
            pd += __shfl_down_sync(0xffffffffu, pd, o, 8);
        }
        if (node < N) {
            float* h2 = g_scratch + OFF_H2 + (size_t)node * 40 + c * 5;
            #pragma unroll
            for (int j = 0; j < 5; j++) h2[j] = acc[i][j];
            if (c == 0) {
                g_scratch[OFF_AS2 + node] = pa;
                g_scratch[OFF_AD2 + node] = pd;
            }
        }
    }
}

// ---------------- layer 2 gather + bias + log_softmax: 8 slots x 4 lanes ----------------
// lane l4 holds classes {l4 + 4j : j=0..9}; slot = lane>>2 owns edge i0+slot.
__global__ void gather2_kernel(const float* __restrict__ b2, float* __restrict__ out, int N) {
    int w = (blockIdx.x * blockDim.x + threadIdx.x) >> 5;
    if (w >= N) return;
    int lane = threadIdx.x & 31;
    int l4 = lane & 3, slot = lane >> 2;
    const int* gi = (const int*)g_scratch;
    int base = gi[IROW + w];
    int deg = gi[IROW + w + 1] - base;
    float ad2 = g_scratch[OFF_AD2 + w];

    float acc[10];
    #pragma unroll
    for (int j = 0; j < 10; j++) acc[j] = 0.f;
    float den = 0.f;

    for (int i0 = 0; i0 < deg; i0 += 8) {
        int idx = i0 + slot;
        bool valid = idx < deg;
        int s = valid ? gi[ICSR + base + idx] : w;
        float as2 = g_scratch[OFF_AS2 + s];
        float ex = valid ? __expf(lrelu(as2 + ad2)) : 0.f;
        const float* h2 = g_scratch + OFF_H2 + (size_t)s * 40;
        #pragma unroll
        for (int j = 0; j < 10; j++) acc[j] = fmaf(ex, h2[l4 + 4 * j], acc[j]);
        den += ex;
    }
    // reduce across 8 slots (xor over bits 2,3,4)
    #pragma unroll
    for (int m = 4; m <= 16; m <<= 1) {
        den += __shfl_xor_sync(0xffffffffu, den, m);
        #pragma unroll
        for (int j = 0; j < 10; j++) acc[j] += __shfl_xor_sync(0xffffffffu, acc[j], m);
    }
    float inv = __frcp_rn(den);
    float v[10];
    #pragma unroll
    for (int j = 0; j < 10; j++) v[j] = acc[j] * inv + __ldg(&b2[l4 + 4 * j]);

    // log_softmax over 40 = 4 lanes x 10 regs (slot-replicated)
    float m0 = v[0];
    #pragma unroll
    for (int j = 1; j < 10; j++) m0 = fmaxf(m0, v[j]);
    #pragma unroll
    for (int o = 1; o <= 2; o <<= 1) m0 = fmaxf(m0, __shfl_xor_sync(0xffffffffu, m0, o));
    float se = 0.f;
    #pragma unroll
    for (int j = 0; j < 10; j++) se += __expf(v[j] - m0);
    #pragma unroll
    for (int o = 1; o <= 2; o <<= 1) se += __shfl_xor_sync(0xffffffffu, se, o);
    float lse = m0 + logf(se);
    if (slot == 0) {
        #pragma unroll
        for (int j = 0; j < 10; j++) out[(size_t)w * 40 + l4 + 4 * j] = v[j] - lse;
    }
}

// ---------------- launch ----------------
extern "C" void kernel_launch(void* const* d_in, const int* in_sizes, int n_in,
                              void* d_out, int out_size) {
    const float* x      = (const float*)d_in[0];
    const int*   ei     = (const int*)d_in[1];
    const float* W1     = (const float*)d_in[2];
    const float* a_src1 = (const float*)d_in[3];
    const float* a_dst1 = (const float*)d_in[4];
    const float* b1     = (const float*)d_in[5];
    const float* W2     = (const float*)d_in[6];
    const float* a_src2 = (const float*)d_in[7];
    const float* a_dst2 = (const float*)d_in[8];
    const float* b2     = (const float*)d_in[9];
    float* out = (float*)d_out;

    int N = in_sizes[0] / F_IN;
    int E = in_sizes[1] / 2;
    int Etot = E + N;
    int nb = (N + 1023) / 1024;

    // CSR build; gemm1 moved to 4th launch (CSR-independent) so ncu profiles it
    zero_int_kernel<<<512, 256>>>(N);
    hist_kernel<<<(Etot + 255) / 256, 256>>>(ei, E, Etot, N);
    scanA_kernel<<<nb, 1024>>>(N);
    gemm1_kernel<<<(N + 255) / 256, 256>>>(x, W1, a_src1, a_dst1, N);
    scanB_kernel<<<1, 1024>>>(nb);
    scanC_kernel<<<(N + 255) / 256, 256>>>(N, Etot);
    scatter_kernel<<<(Etot + 255) / 256, 256>>>(ei, E, Etot, N);

    gather1_kernel<<<(N * 32 + 255) / 256, 256>>>(N);
    gemm2_kernel<<<(N + 255) / 256, 256>>>(W2, a_src2, a_dst2, b1, N);
    gather2_kernel<<<(N * 32 + 255) / 256, 256>>>(b2, out, N);
}

// round 17
// speedup vs baseline: 1.0470x; 1.0470x over previous
#include <cuda_runtime.h>
#include <cuda_bf16.h>
#include <math.h>

// ---------------- problem constants ----------------
#define F_IN   256
#define HEADS  8
#define HID    8
#define D1     64
#define CLS    40
#define NEG_SLOPE 0.2f

// ---------------- scratch layout ----------------
#define OFF_H1      0ull                 // N*64 floats
#define OFF_AS1     6400000ull           // N*8
#define OFF_AD1     7200000ull           // N*8
#define OFF_H2      8000000ull           // N*40
#define OFF_AS2     12000000ull          // N
#define OFF_AD2     12100000ull          // N
#define OFF_AGG1    12200000ull          // N*64 (normalized, written by gather1)
// int regions (indices into (int*)g_scratch)
#define ICNT        18600000u            // N
#define IROW        18800000u            // N+1
#define ICUR        19000000u            // N
#define ICSR        19200000u            // Etot
#define IPART       21200000u            // <= 1024
#define TOTAL_SCR   23500000ull

__device__ __align__(16) float g_scratch[TOTAL_SCR];

__device__ __forceinline__ float lrelu(float v) { return v > 0.f ? v : NEG_SLOPE * v; }

// ---------------- CSR build ----------------
__global__ void zero_int_kernel(int N) {
    int* gi = (int*)g_scratch;
    int i = blockIdx.x * blockDim.x + threadIdx.x;
    int stride = gridDim.x * blockDim.x;
    for (; i < 2 * N; i += stride) {
        if (i < N) gi[ICNT + i] = 0;
        else       gi[ICUR + (i - N)] = 0;
    }
}

__global__ void hist_kernel(const int* __restrict__ ei, int E, int Etot, int N) {
    int e = blockIdx.x * blockDim.x + threadIdx.x;
    if (e >= Etot) return;
    int d = (e < E) ? ei[E + e] : (e - E);
    if ((unsigned)d >= (unsigned)N) return;
    atomicAdd((int*)g_scratch + ICNT + d, 1);
}

__global__ void scanA_kernel(int N) {
    __shared__ int sh[1024];
    int* gi = (int*)g_scratch;
    int t = threadIdx.x, b = blockIdx.x;
    int i = b * 1024 + t;
    int v = (i < N) ? gi[ICNT + i] : 0;
    sh[t] = v;
    __syncthreads();
    for (int off = 1; off < 1024; off <<= 1) {
        int x = (t >= off) ? sh[t - off] : 0;
        __syncthreads();
        sh[t] += x;
        __syncthreads();
    }
    if (i < N) gi[IROW + i] = sh[t] - v;
    if (t == 1023) gi[IPART + b] = sh[1023];
}

__global__ void scanB_kernel(int nb) {
    __shared__ int sh[1024];
    int* gi = (int*)g_scratch;
    int t = threadIdx.x;
    int v = (t < nb) ? gi[IPART + t] : 0;
    sh[t] = v;
    __syncthreads();
    for (int off = 1; off < 1024; off <<= 1) {
        int x = (t >= off) ? sh[t - off] : 0;
        __syncthreads();
        sh[t] += x;
        __syncthreads();
    }
    if (t < nb) gi[IPART + t] = sh[t] - v;
}

__global__ void scanC_kernel(int N, int Etot) {
    int* gi = (int*)g_scratch;
    int i = blockIdx.x * blockDim.x + threadIdx.x;
    if (i < N) gi[IROW + i] += gi[IPART + (i >> 10)];
    if (i == 0) gi[IROW + N] = Etot;
}

__global__ void scatter_kernel(const int* __restrict__ ei, int E, int Etot, int N) {
    int e = blockIdx.x * blockDim.x + threadIdx.x;
    if (e >= Etot) return;
    int s, d;
    if (e < E) { s = ei[e]; d = ei[E + e]; } else { s = d = e - E; }
    if ((unsigned)s >= (unsigned)N || (unsigned)d >= (unsigned)N) return;
    int* gi = (int*)g_scratch;
    int pos = atomicAdd(gi + ICUR + d, 1);
    gi[ICSR + gi[IROW + d] + pos] = s;
}

// ---------------- layer 1 GEMM (register tiled, occupancy-tuned) + logits ----------------
// Tile: 128 nodes x 64 outs. 256 threads: r=t>>3 (4-node group), c=t&7 (head).
// acc 4x8 = 32 regs -> ~3 blocks/SM instead of 1 (was 141 regs, occ 12.5%).
__global__ void gemm1_kernel(const float* __restrict__ x, const float* __restrict__ W1,
                             const float* __restrict__ a_src, const float* __restrict__ a_dst,
                             int N) {
    __shared__ __align__(16) float xs[128 * 33];   // 16.9KB
    __shared__ __align__(16) float Ws[32 * 68];    //  8.7KB
    int t = threadIdx.x;
    int node0 = blockIdx.x * 128;
    int r = t >> 3, c = t & 7;

    float acc[4][8];
    #pragma unroll
    for (int i = 0; i < 4; i++)
        #pragma unroll
        for (int j = 0; j < 8; j++) acc[i][j] = 0.f;

    for (int kt = 0; kt < 8; kt++) {
        __syncthreads();
        // x chunk: 128 nodes x 8 float4 = 1024 float4
        #pragma unroll
        for (int p = 0; p < 4; p++) {
            int i = t + p * 256;
            int nl = i >> 3, q = i & 7;
            int nd = node0 + nl;
            float4 v = make_float4(0.f, 0.f, 0.f, 0.f);
            if (nd < N) v = ((const float4*)x)[(size_t)nd * 64 + kt * 8 + q];
            float* dp = &xs[nl * 33 + q * 4];
            dp[0] = v.x; dp[1] = v.y; dp[2] = v.z; dp[3] = v.w;
        }
        // W chunk: 32 k x 64 out = 512 float4
        #pragma unroll
        for (int p = 0; p < 2; p++) {
            int i = t + p * 256;
            int k = i >> 4, o4 = i & 15;
            float4 v = ((const float4*)W1)[(size_t)(kt * 32 + k) * 16 + o4];
            float* dp = &Ws[k * 68 + o4 * 4];
            dp[0] = v.x; dp[1] = v.y; dp[2] = v.z; dp[3] = v.w;
        }
        __syncthreads();

        #pragma unroll 4
        for (int kk = 0; kk < 32; kk++) {
            float wv[8];
            *(float4*)wv       = *(const float4*)&Ws[kk * 68 + c * 8];
            *(float4*)(wv + 4) = *(const float4*)&Ws[kk * 68 + c * 8 + 4];
            float xv[4];
            #pragma unroll
            for (int i = 0; i < 4; i++) xv[i] = xs[(r * 4 + i) * 33 + kk];
            #pragma unroll
            for (int i = 0; i < 4; i++)
                #pragma unroll
                for (int j = 0; j < 8; j++) acc[i][j] = fmaf(xv[i], wv[j], acc[i][j]);
        }
    }

    float asw[8], adw[8];
    #pragma unroll
    for (int j = 0; j < 8; j++) {
        asw[j] = __ldg(&a_src[c * 8 + j]);
        adw[j] = __ldg(&a_dst[c * 8 + j]);
    }
    #pragma unroll
    for (int i = 0; i < 4; i++) {
        int node = node0 + r * 4 + i;
        if (node < N) {
            float* h1 = g_scratch + OFF_H1 + (size_t)node * 64 + c * 8;
            ((float4*)h1)[0] = make_float4(acc[i][0], acc[i][1], acc[i][2], acc[i][3]);
            ((float4*)h1)[1] = make_float4(acc[i][4], acc[i][5], acc[i][6], acc[i][7]);
            float as = 0.f, ad = 0.f;
            #pragma unroll
            for (int j = 0; j < 8; j++) {
                as = fmaf(acc[i][j], asw[j], as);
                ad = fmaf(acc[i][j], adw[j], ad);
            }
            g_scratch[OFF_AS1 + (size_t)node * 8 + c] = as;
            g_scratch[OFF_AD1 + (size_t)node * 8 + c] = ad;
        }
    }
}

// ---------------- layer 1 gather (R15 verbatim): 4 edge-slots x 8 lanes ----------------
// lane l = lane&7 owns head l (channels l*8..l*8+7); slot = lane>>3 owns edge i0+slot.
__global__ void gather1_kernel(int N) {
    int w = (blockIdx.x * blockDim.x + threadIdx.x) >> 5;
    if (w >= N) return;
    int lane = threadIdx.x & 31;
    int l = lane & 7, slot = lane >> 3;
    const int* gi = (const int*)g_scratch;
    int base = gi[IROW + w];
    int deg = gi[IROW + w + 1] - base;
    float ad = g_scratch[OFF_AD1 + (size_t)w * 8 + l];

    float acc[8];
    #pragma unroll
    for (int j = 0; j < 8; j++) acc[j] = 0.f;
    float den = 0.f;

    for (int i0 = 0; i0 < deg; i0 += 4) {
        int idx = i0 + slot;
        bool valid = idx < deg;
        int s = valid ? gi[ICSR + base + idx] : w;
        float as = g_scratch[OFF_AS1 + (size_t)s * 8 + l];
        float ex = valid ? __expf(lrelu(as + ad)) : 0.f;
        const float4* hv = (const float4*)(g_scratch + OFF_H1 + (size_t)s * 64 + l * 8);
        float4 v0 = hv[0], v1 = hv[1];
        acc[0] = fmaf(ex, v0.x, acc[0]); acc[1] = fmaf(ex, v0.y, acc[1]);
        acc[2] = fmaf(ex, v0.z, acc[2]); acc[3] = fmaf(ex, v0.w, acc[3]);
        acc[4] = fmaf(ex, v1.x, acc[4]); acc[5] = fmaf(ex, v1.y, acc[5]);
        acc[6] = fmaf(ex, v1.z, acc[6]); acc[7] = fmaf(ex, v1.w, acc[7]);
        den += ex;
    }
    #pragma unroll
    for (int m = 8; m <= 16; m <<= 1) {
        den += __shfl_xor_sync(0xffffffffu, den, m);
        #pragma unroll
        for (int j = 0; j < 8; j++) acc[j] += __shfl_xor_sync(0xffffffffu, acc[j], m);
    }
    if (slot == 0) {
        float inv = __frcp_rn(den);
        float* dst = g_scratch + OFF_AGG1 + (size_t)w * 64 + l * 8;
        ((float4*)dst)[0] = make_float4(acc[0] * inv, acc[1] * inv, acc[2] * inv, acc[3] * inv);
        ((float4*)dst)[1] = make_float4(acc[4] * inv, acc[5] * inv, acc[6] * inv, acc[7] * inv);
    }
}

// ---------------- ELU + layer 2 GEMM (register tiled) + logits ----------------
// Tile: 256 nodes x 40 outs. 256 threads: r=t>>3, c=t&7 (classes c*5..c*5+4).
__global__ void gemm2_kernel(const float* __restrict__ W2, const float* __restrict__ a_src2,
                             const float* __restrict__ a_dst2, const float* __restrict__ b1,
                             int N) {
    __shared__ __align__(16) float xs[256 * 33];
    __shared__ __align__(16) float Ws[32 * 44];
    int t = threadIdx.x;
    int node0 = blockIdx.x * 256;
    int r = t >> 3, c = t & 7;

    float acc[8][5];
    #pragma unroll
    for (int i = 0; i < 8; i++)
        #pragma unroll
        for (int j = 0; j < 5; j++) acc[i][j] = 0.f;

    for (int kt = 0; kt < 2; kt++) {
        __syncthreads();
        #pragma unroll
        for (int p = 0; p < 8; p++) {
            int i = t + p * 256;
            int nl = i >> 3, q = i & 7;
            int nd = node0 + nl;
            float4 v = make_float4(0.f, 0.f, 0.f, 0.f);
            if (nd < N) {
                v = *(const float4*)(g_scratch + OFF_AGG1 + (size_t)nd * 64 + kt * 32 + q * 4);
                float4 bv = *(const float4*)&b1[kt * 32 + q * 4];
                v.x += bv.x; v.y += bv.y; v.z += bv.z; v.w += bv.w;
                v.x = v.x > 0.f ? v.x : expm1f(v.x);
                v.y = v.y > 0.f ? v.y : expm1f(v.y);
                v.z = v.z > 0.f ? v.z : expm1f(v.z);
                v.w = v.w > 0.f ? v.w : expm1f(v.w);
            }
            float* dp = &xs[nl * 33 + q * 4];
            dp[0] = v.x; dp[1] = v.y; dp[2] = v.z; dp[3] = v.w;
        }
        for (int i = t; i < 320; i += 256) {
            int k = i / 10, o4 = i % 10;
            float4 v = ((const float4*)W2)[(size_t)(kt * 32 + k) * 10 + o4];
            float* dp = &Ws[k * 44 + o4 * 4];
            dp[0] = v.x; dp[1] = v.y; dp[2] = v.z; dp[3] = v.w;
        }
        __syncthreads();

        #pragma unroll 4
        for (int kk = 0; kk < 32; kk++) {
            float wv[5];
            #pragma unroll
            for (int j = 0; j < 5; j++) wv[j] = Ws[kk * 44 + c * 5 + j];
            float xv[8];
            #pragma unroll
            for (int i = 0; i < 8; i++) xv[i] = xs[(r * 8 + i) * 33 + kk];
            #pragma unroll
            for (int i = 0; i < 8; i++)
                #pragma unroll
                for (int j = 0; j < 5; j++) acc[i][j] = fmaf(xv[i], wv[j], acc[i][j]);
        }
    }

    float a2s[5], a2d[5];
    #pragma unroll
    for (int j = 0; j < 5; j++) {
        a2s[j] = __ldg(&a_src2[c * 5 + j]);
        a2d[j] = __ldg(&a_dst2[c * 5 + j]);
    }
    #pragma unroll
    for (int i = 0; i < 8; i++) {
        int node = node0 + r * 8 + i;
        float pa = 0.f, pd = 0.f;
        #pragma unroll
        for (int j = 0; j < 5; j++) {
            pa = fmaf(acc[i][j], a2s[j], pa);
            pd = fmaf(acc[i][j], a2d[j], pd);
        }
        #pragma unroll
        for (int o = 4; o >= 1; o >>= 1) {
            pa += __shfl_down_sync(0xffffffffu, pa, o, 8);
            pd += __shfl_down_sync(0xffffffffu, pd, o, 8);
        }
        if (node < N) {
            float* h2 = g_scratch + OFF_H2 + (size_t)node * 40 + c * 5;
            #pragma unroll
            for (int j = 0; j < 5; j++) h2[j] = acc[i][j];
            if (c == 0) {
                g_scratch[OFF_AS2 + node] = pa;
                g_scratch[OFF_AD2 + node] = pd;
            }
        }
    }
}

// ---------------- layer 2 gather + bias + log_softmax (R15 verbatim): 4 slots x 8 lanes ----------------
// lane l holds classes {l, l+8, l+16, l+24, l+32}; slot owns edge i0+slot.
__global__ void gather2_kernel(const float* __restrict__ b2, float* __restrict__ out, int N) {
    int w = (blockIdx.x * blockDim.x + threadIdx.x) >> 5;
    if (w >= N) return;
    int lane = threadIdx.x & 31;
    int l = lane & 7, slot = lane >> 3;
    const int* gi = (const int*)g_scratch;
    int base = gi[IROW + w];
    int deg = gi[IROW + w + 1] - base;
    float ad2 = g_scratch[OFF_AD2 + w];

    float acc[5];
    #pragma unroll
    for (int j = 0; j < 5; j++) acc[j] = 0.f;
    float den = 0.f;

    for (int i0 = 0; i0 < deg; i0 += 4) {
        int idx = i0 + slot;
        bool valid = idx < deg;
        int s = valid ? gi[ICSR + base + idx] : w;
        float as2 = g_scratch[OFF_AS2 + s];
        float ex = valid ? __expf(lrelu(as2 + ad2)) : 0.f;
        const float* h2 = g_scratch + OFF_H2 + (size_t)s * 40;
        #pragma unroll
        for (int j = 0; j < 5; j++) acc[j] = fmaf(ex, h2[l + 8 * j], acc[j]);
        den += ex;
    }
    #pragma unroll
    for (int m = 8; m <= 16; m <<= 1) {
        den += __shfl_xor_sync(0xffffffffu, den, m);
        #pragma unroll
        for (int j = 0; j < 5; j++) acc[j] += __shfl_xor_sync(0xffffffffu, acc[j], m);
    }
    float inv = __frcp_rn(den);
    float v[5];
    #pragma unroll
    for (int j = 0; j < 5; j++) v[j] = acc[j] * inv + __ldg(&b2[l + 8 * j]);

    float m0 = v[0];
    #pragma unroll
    for (int j = 1; j < 5; j++) m0 = fmaxf(m0, v[j]);
    #pragma unroll
    for (int o = 1; o <= 4; o <<= 1) m0 = fmaxf(m0, __shfl_xor_sync(0xffffffffu, m0, o));
    float se = 0.f;
    #pragma unroll
    for (int j = 0; j < 5; j++) se += __expf(v[j] - m0);
    #pragma unroll
    for (int o = 1; o <= 4; o <<= 1) se += __shfl_xor_sync(0xffffffffu, se, o);
    float lse = m0 + logf(se);
    if (slot == 0) {
        #pragma unroll
        for (int j = 0; j < 5; j++) out[(size_t)w * 40 + l + 8 * j] = v[j] - lse;
    }
}

// ---------------- launch ----------------
extern "C" void kernel_launch(void* const* d_in, const int* in_sizes, int n_in,
                              void* d_out, int out_size) {
    const float* x      = (const float*)d_in[0];
    const int*   ei     = (const int*)d_in[1];
    const float* W1     = (const float*)d_in[2];
    const float* a_src1 = (const float*)d_in[3];
    const float* a_dst1 = (const float*)d_in[4];
    const float* b1     = (const float*)d_in[5];
    const float* W2     = (const float*)d_in[6];
    const float* a_src2 = (const float*)d_in[7];
    const float* a_dst2 = (const float*)d_in[8];
    const float* b2     = (const float*)d_in[9];
    float* out = (float*)d_out;

    int N = in_sizes[0] / F_IN;
    int E = in_sizes[1] / 2;
    int Etot = E + N;
    int nb = (N + 1023) / 1024;

    // CSR build; gemm1 stays 4th launch (CSR-independent) so ncu profiles it
    zero_int_kernel<<<512, 256>>>(N);
    hist_kernel<<<(Etot + 255) / 256, 256>>>(ei, E, Etot, N);
    scanA_kernel<<<nb, 1024>>>(N);
    gemm1_kernel<<<(N + 127) / 128, 256>>>(x, W1, a_src1, a_dst1, N);
    scanB_kernel<<<1, 1024>>>(nb);
    scanC_kernel<<<(N + 255) / 256, 256>>>(N, Etot);
    scatter_kernel<<<(Etot + 255) / 256, 256>>>(ei, E, Etot, N);

    gather1_kernel<<<(N * 32 + 255) / 256, 256>>>(N);
    gemm2_kernel<<<(N + 255) / 256, 256>>>(W2, a_src2, a_dst2, b1, N);
    gather2_kernel<<<(N * 32 + 255) / 256, 256>>>(b2, out, N);
}